// round 11
// baseline (speedup 1.0000x reference)
#include <cuda_runtime.h>
#include <math.h>

#define NATOMS 20000
#define MBEADS 2000
#define EHALF  160000
#define FD     128
#define NRBF   16
#define PIF    3.14159265358979323846f

// ---------------- scratch (device globals; no allocation allowed) -------------
__device__ float g_h[NATOMS * FD];      // node features (updated in place)
__device__ float g_hid[NATOMS * FD];    // silu hidden
__device__ float g_phi[NATOMS * FD];    // phi (first F columns only)
__device__ float g_H[MBEADS * FD];      // bead accumulator
__device__ float g_cnt[MBEADS];
__device__ float g_icnt[MBEADS];
__device__ float g_eemb[EHALF * 17];    // per-edge: rbf*env (16) + env
__device__ float g_aemb[NATOMS * 17];   // per-atom (CG cutoff): rbf*env (16) + env

// vectorized global reduction (sm_90+)
__device__ __forceinline__ void red4(float* addr, float x, float y, float z, float w) {
    asm volatile("red.global.add.v4.f32 [%0], {%1,%2,%3,%4};"
                 :: "l"(addr), "f"(x), "f"(y), "f"(z), "f"(w) : "memory");
}

// ---------------- init / precompute ----------------
__global__ void k_zero() {
    int i = blockIdx.x * blockDim.x + threadIdx.x;
    if (i < MBEADS * FD) g_H[i] = 0.f;
    if (i < MBEADS) g_cnt[i] = 0.f;
}

__global__ void k_init(const int* __restrict__ z, const int* __restrict__ cg_z,
                       const int* __restrict__ map,
                       const float* __restrict__ emb_atom,
                       const float* __restrict__ emb_res) {
    int idx = blockIdx.x * blockDim.x + threadIdx.x;
    if (idx >= NATOMS * 32) return;
    int a = idx >> 5, c = idx & 31;
    int f = c * 4;
    float4 v;
    if (f < 64) v = *(const float4*)(emb_atom + (size_t)z[a] * 64 + f);
    else        v = *(const float4*)(emb_res + (size_t)cg_z[map[a]] * 64 + (f - 64));
    *(float4*)(g_h + (size_t)a * FD + f) = v;
    if (c == 0) atomicAdd(&g_cnt[map[a]], 1.0f);
}

__global__ void k_icnt() {
    int m = blockIdx.x * blockDim.x + threadIdx.x;
    if (m < MBEADS) g_icnt[m] = 1.0f / fmaxf(g_cnt[m], 1.0f);
}

__device__ __forceinline__ void rbf_env(float d, float cut, float* out17) {
    float env = 0.f;
    if (d < cut) env = 0.5f * (cosf(PIF * d / cut) + 1.0f);
    if (env == 0.f) {
        #pragma unroll
        for (int k = 0; k < 17; k++) out17[k] = 0.f;
        return;
    }
    float invd = 1.0f / d;
    float w = PIF / cut * d;
    #pragma unroll
    for (int k = 0; k < 16; k++)
        out17[k] = env * sinf((float)(k + 1) * w) * invd;
    out17[16] = env;
}

__global__ void k_epre(const int* __restrict__ nbr, const float* __restrict__ xyz) {
    int e = blockIdx.x * blockDim.x + threadIdx.x;
    if (e >= EHALF) return;
    int a = nbr[2 * e], b = nbr[2 * e + 1];
    float dx = xyz[3 * b + 0] - xyz[3 * a + 0];
    float dy = xyz[3 * b + 1] - xyz[3 * a + 1];
    float dz = xyz[3 * b + 2] - xyz[3 * a + 2];
    float d = sqrtf(dx * dx + dy * dy + dz * dz + 3e-15f);
    float o[17];
    rbf_env(d, 5.0f, o);
    #pragma unroll
    for (int k = 0; k < 17; k++) g_eemb[(size_t)e * 17 + k] = o[k];
}

__global__ void k_aemb(const int* __restrict__ map, const float* __restrict__ xyz,
                       const float* __restrict__ cg_xyz) {
    int a = blockIdx.x * blockDim.x + threadIdx.x;
    if (a >= NATOMS) return;
    int m = map[a];
    float dx = xyz[3 * a + 0] - cg_xyz[3 * m + 0];
    float dy = xyz[3 * a + 1] - cg_xyz[3 * m + 1];
    float dz = xyz[3 * a + 2] - cg_xyz[3 * m + 2];
    float d = sqrtf(dx * dx + dy * dy + dz * dz + 3e-15f);
    float o[17];
    rbf_env(d, 20.0f, o);
    #pragma unroll
    for (int k = 0; k < 17; k++) g_aemb[(size_t)a * 17 + k] = o[k];
}

// ---------------- SGEMM: C[n,128] = A[n,128] @ W[128, ldw][:, :128] + bias ----
// 256 threads, 64-row x 128-col tile, thread micro-tile 8x4, BK=32.
__global__ void k_gemm(const float* __restrict__ A, const float* __restrict__ W,
                       int ldw, const float* __restrict__ bias,
                       float* __restrict__ C, int n, int dosilu) {
    __shared__ float As[32 * 68];   // transposed A tile [kk][row], padded
    __shared__ float Ws[32 * 128];  // W tile [kk][col]
    int tid = threadIdx.x;
    int tx = tid & 31, ty = tid >> 5;
    int row0 = blockIdx.x * 64;
    float acc[8][4];
    #pragma unroll
    for (int i = 0; i < 8; i++)
        #pragma unroll
        for (int j = 0; j < 4; j++) acc[i][j] = 0.f;

    for (int k0 = 0; k0 < 128; k0 += 32) {
        #pragma unroll
        for (int j = 0; j < 2; j++) {
            int q = tid + j * 256;
            int r = q >> 3, c4 = q & 7;
            float4 v = make_float4(0.f, 0.f, 0.f, 0.f);
            if (row0 + r < n)
                v = *(const float4*)(A + (size_t)(row0 + r) * 128 + k0 + c4 * 4);
            As[(c4 * 4 + 0) * 68 + r] = v.x;
            As[(c4 * 4 + 1) * 68 + r] = v.y;
            As[(c4 * 4 + 2) * 68 + r] = v.z;
            As[(c4 * 4 + 3) * 68 + r] = v.w;
        }
        #pragma unroll
        for (int j = 0; j < 4; j++) {
            int q = tid + j * 256;
            int kk = q >> 5, c4 = q & 31;
            *(float4*)(Ws + kk * 128 + c4 * 4) =
                *(const float4*)(W + (size_t)(k0 + kk) * ldw + c4 * 4);
        }
        __syncthreads();
        #pragma unroll
        for (int kk = 0; kk < 32; kk++) {
            float4 a0 = *(const float4*)(As + kk * 68 + ty * 8);
            float4 a1 = *(const float4*)(As + kk * 68 + ty * 8 + 4);
            float4 b  = *(const float4*)(Ws + kk * 128 + tx * 4);
            float av[8] = {a0.x, a0.y, a0.z, a0.w, a1.x, a1.y, a1.z, a1.w};
            float bv[4] = {b.x, b.y, b.z, b.w};
            #pragma unroll
            for (int i = 0; i < 8; i++)
                #pragma unroll
                for (int j = 0; j < 4; j++)
                    acc[i][j] += av[i] * bv[j];
        }
        __syncthreads();
    }

    float4 bq = *(const float4*)(bias + tx * 4);
    float bb[4] = {bq.x, bq.y, bq.z, bq.w};
    #pragma unroll
    for (int i = 0; i < 8; i++) {
        int r = row0 + ty * 8 + i;
        if (r < n) {
            float o[4];
            #pragma unroll
            for (int j = 0; j < 4; j++) {
                float x = acc[i][j] + bb[j];
                if (dosilu) x = x / (1.0f + __expf(-x));
                o[j] = x;
            }
            *(float4*)(C + (size_t)r * 128 + tx * 4) =
                make_float4(o[0], o[1], o[2], o[3]);
        }
    }
}

// ---------------- edge message pass: h[a] += emb*phi[b]; h[b] += emb*phi[a] ---
__global__ void k_edge_conv(const int* __restrict__ nbr,
                            const float* __restrict__ Wd,   // (16, 384) use cols<128
                            const float* __restrict__ bd) { // (384)     use <128
    __shared__ float sW[16 * 128];
    __shared__ float sb[128];
    for (int t = threadIdx.x; t < 16 * 128; t += blockDim.x)
        sW[t] = Wd[(t >> 7) * 384 + (t & 127)];
    if (threadIdx.x < 128) sb[threadIdx.x] = bd[threadIdx.x];
    __syncthreads();

    int lane = threadIdx.x & 31;
    int w  = (blockIdx.x * blockDim.x + threadIdx.x) >> 5;
    int nw = (gridDim.x * blockDim.x) >> 5;
    float4 bv = *(const float4*)(sb + lane * 4);

    for (int e = w; e < EHALF; e += nw) {
        float rv = (lane < 17) ? g_eemb[(size_t)e * 17 + lane] : 0.f;
        float env = __shfl_sync(0xffffffffu, rv, 16);
        if (env == 0.f) continue;   // uniform across warp
        int a = nbr[2 * e], b = nbr[2 * e + 1];
        float ex = env * bv.x, ey = env * bv.y, ez = env * bv.z, ew = env * bv.w;
        #pragma unroll
        for (int k = 0; k < 16; k++) {
            float r = __shfl_sync(0xffffffffu, rv, k);
            float4 wv = *(const float4*)(sW + k * 128 + lane * 4);
            ex += r * wv.x; ey += r * wv.y; ez += r * wv.z; ew += r * wv.w;
        }
        float4 pb = *(const float4*)(g_phi + (size_t)b * FD + lane * 4);
        float4 pa = *(const float4*)(g_phi + (size_t)a * FD + lane * 4);
        red4(g_h + (size_t)a * FD + lane * 4, ex * pb.x, ey * pb.y, ez * pb.z, ew * pb.w);
        red4(g_h + (size_t)b * FD + lane * 4, ex * pa.x, ey * pa.y, ez * pa.z, ew * pa.w);
    }
}

// ---------------- CG pass: H[map[a]] += emb(d_iI)*phi[a] / cnt ---------------
__global__ void k_cg_conv(const int* __restrict__ map,
                          const float* __restrict__ Wd,
                          const float* __restrict__ bd) {
    __shared__ float sW[16 * 128];
    __shared__ float sb[128];
    for (int t = threadIdx.x; t < 16 * 128; t += blockDim.x)
        sW[t] = Wd[(t >> 7) * 384 + (t & 127)];
    if (threadIdx.x < 128) sb[threadIdx.x] = bd[threadIdx.x];
    __syncthreads();

    int lane = threadIdx.x & 31;
    int w  = (blockIdx.x * blockDim.x + threadIdx.x) >> 5;
    int nw = (gridDim.x * blockDim.x) >> 5;
    float4 bv = *(const float4*)(sb + lane * 4);

    for (int a = w; a < NATOMS; a += nw) {
        float rv = (lane < 17) ? g_aemb[(size_t)a * 17 + lane] : 0.f;
        float env = __shfl_sync(0xffffffffu, rv, 16);
        if (env == 0.f) continue;
        float ex = env * bv.x, ey = env * bv.y, ez = env * bv.z, ew = env * bv.w;
        #pragma unroll
        for (int k = 0; k < 16; k++) {
            float r = __shfl_sync(0xffffffffu, rv, k);
            float4 wv = *(const float4*)(sW + k * 128 + lane * 4);
            ex += r * wv.x; ey += r * wv.y; ez += r * wv.z; ew += r * wv.w;
        }
        float4 p = *(const float4*)(g_phi + (size_t)a * FD + lane * 4);
        int m = map[a];
        float ic = g_icnt[m];
        red4(g_H + (size_t)m * FD + lane * 4,
             ex * p.x * ic, ey * p.y * ic, ez * p.z * ic, ew * p.w * ic);
    }
}

// ---------------- H snapshot after conv0 message update ----------------------
__global__ void k_snapshot(const int* __restrict__ map) {
    int idx = blockIdx.x * blockDim.x + threadIdx.x;
    if (idx >= NATOMS * 32) return;
    int a = idx >> 5, c = idx & 31;
    int m = map[a];
    float ic = g_icnt[m];
    float4 v = *(const float4*)(g_h + (size_t)a * FD + c * 4);
    red4(g_H + (size_t)m * FD + c * 4, v.x * ic, v.y * ic, v.z * ic, v.w * ic);
}

// ---------------- output: [H (M,F), h (N,F)] ---------------------------------
__global__ void k_out(float* __restrict__ out) {
    int idx = blockIdx.x * blockDim.x + threadIdx.x;
    const int nH = MBEADS * FD / 4;
    const int tot = nH + NATOMS * FD / 4;
    if (idx >= tot) return;
    float4 v;
    if (idx < nH) v = ((const float4*)g_H)[idx];
    else          v = ((const float4*)g_h)[idx - nH];
    ((float4*)out)[idx] = v;
}

// ---------------- launch ------------------------------------------------------
extern "C" void kernel_launch(void* const* d_in, const int* in_sizes, int n_in,
                              void* d_out, int out_size) {
    const int*   z        = (const int*)d_in[0];
    const float* xyz      = (const float*)d_in[1];
    const int*   cg_z     = (const int*)d_in[2];
    const float* cg_xyz   = (const float*)d_in[3];
    const int*   mapping  = (const int*)d_in[4];
    const int*   nbr      = (const int*)d_in[5];
    // d_in[6] cg_nbr_list, d_in[7] ic: unused (dead in reference output)
    const float* emb_atom = (const float*)d_in[8];
    const float* emb_res  = (const float*)d_in[9];
    const float* Wm1 = (const float*)d_in[10];
    const float* bm1 = (const float*)d_in[11];
    const float* Wm2 = (const float*)d_in[12];
    const float* bm2 = (const float*)d_in[13];
    const float* Wdm = (const float*)d_in[14];
    const float* bdm = (const float*)d_in[15];
    const float* Wc1 = (const float*)d_in[16];
    const float* bc1 = (const float*)d_in[17];
    const float* Wc2 = (const float*)d_in[18];
    const float* bc2 = (const float*)d_in[19];
    const float* Wdc = (const float*)d_in[20];
    const float* bdc = (const float*)d_in[21];

    float *ph = nullptr, *phid = nullptr, *pphi = nullptr;
    cudaGetSymbolAddress((void**)&ph, g_h);
    cudaGetSymbolAddress((void**)&phid, g_hid);
    cudaGetSymbolAddress((void**)&pphi, g_phi);

    k_zero<<<(MBEADS * FD + 255) / 256, 256>>>();
    k_init<<<(NATOMS * 32 + 255) / 256, 256>>>(z, cg_z, mapping, emb_atom, emb_res);
    k_icnt<<<(MBEADS + 255) / 256, 256>>>();
    k_epre<<<(EHALF + 255) / 256, 256>>>(nbr, xyz);
    k_aemb<<<(NATOMS + 255) / 256, 256>>>(mapping, xyz, cg_xyz);

    const int gb = (NATOMS + 63) / 64;
    for (int i = 0; i < 2; i++) {
        // message block: phi = silu(h@Wm1+bm1)@Wm2[:, :F]+bm2[:F]
        k_gemm<<<gb, 256>>>(ph,   Wm1 + (size_t)i * 128 * 128, 128, bm1 + i * 128, phid, NATOMS, 1);
        k_gemm<<<gb, 256>>>(phid, Wm2 + (size_t)i * 128 * 384, 384, bm2 + i * 384, pphi, NATOMS, 0);
        k_edge_conv<<<592, 256>>>(nbr, Wdm + (size_t)i * 16 * 384, bdm + i * 384);
        if (i == 0)
            k_snapshot<<<(NATOMS * 32 + 255) / 256, 256>>>(mapping);
        // CG block: only s0 feeds H
        k_gemm<<<gb, 256>>>(ph,   Wc1 + (size_t)i * 128 * 128, 128, bc1 + i * 128, phid, NATOMS, 1);
        k_gemm<<<gb, 256>>>(phid, Wc2 + (size_t)i * 128 * 384, 384, bc2 + i * 384, pphi, NATOMS, 0);
        k_cg_conv<<<592, 256>>>(mapping, Wdc + (size_t)i * 16 * 384, bdc + i * 384);
    }
    k_out<<<((MBEADS + NATOMS) * 32 + 255) / 256, 256>>>((float*)d_out);
}

// round 12
// speedup vs baseline: 1.0044x; 1.0044x over previous
#include <cuda_runtime.h>
#include <math.h>

#define NATOMS 20000
#define MBEADS 2000
#define EHALF  160000
#define FD     128
#define NRBF   16
#define PIF    3.14159265358979323846f

// ---------------- scratch (device globals; no allocation allowed) -------------
__device__ float g_h[NATOMS * FD];      // node features (updated in place)
__device__ float g_hid[NATOMS * FD];    // silu hidden
__device__ float g_phi[NATOMS * FD];    // phi (first F columns only)
__device__ float g_H[MBEADS * FD];      // bead accumulator
__device__ float g_cnt[MBEADS];
__device__ float g_icnt[MBEADS];
__device__ float g_eemb[EHALF * 17];    // per-edge: rbf*env (16) + env
__device__ float g_aemb[NATOMS * 17];   // per-atom (CG cutoff): rbf*env (16) + env

// vectorized global reduction (sm_90+)
__device__ __forceinline__ void red4(float* addr, float x, float y, float z, float w) {
    asm volatile("red.global.add.v4.f32 [%0], {%1,%2,%3,%4};"
                 :: "l"(addr), "f"(x), "f"(y), "f"(z), "f"(w) : "memory");
}

// ---------------- init / precompute ----------------
__global__ void k_zero() {
    int i = blockIdx.x * blockDim.x + threadIdx.x;
    if (i < MBEADS * FD) g_H[i] = 0.f;
    if (i < MBEADS) g_cnt[i] = 0.f;
}

__global__ void k_init(const int* __restrict__ z, const int* __restrict__ cg_z,
                       const int* __restrict__ map,
                       const float* __restrict__ emb_atom,
                       const float* __restrict__ emb_res) {
    int idx = blockIdx.x * blockDim.x + threadIdx.x;
    if (idx >= NATOMS * 32) return;
    int a = idx >> 5, c = idx & 31;
    int f = c * 4;
    float4 v;
    if (f < 64) v = *(const float4*)(emb_atom + (size_t)z[a] * 64 + f);
    else        v = *(const float4*)(emb_res + (size_t)cg_z[map[a]] * 64 + (f - 64));
    *(float4*)(g_h + (size_t)a * FD + f) = v;
    if (c == 0) atomicAdd(&g_cnt[map[a]], 1.0f);
}

__global__ void k_icnt() {
    int m = blockIdx.x * blockDim.x + threadIdx.x;
    if (m < MBEADS) g_icnt[m] = 1.0f / fmaxf(g_cnt[m], 1.0f);
}

__device__ __forceinline__ void rbf_env(float d, float cut, float* out17) {
    float env = 0.f;
    if (d < cut) env = 0.5f * (cosf(PIF * d / cut) + 1.0f);
    if (env == 0.f) {
        #pragma unroll
        for (int k = 0; k < 17; k++) out17[k] = 0.f;
        return;
    }
    float invd = 1.0f / d;
    float w = PIF / cut * d;
    #pragma unroll
    for (int k = 0; k < 16; k++)
        out17[k] = env * sinf((float)(k + 1) * w) * invd;
    out17[16] = env;
}

__global__ void k_epre(const int* __restrict__ nbr, const float* __restrict__ xyz) {
    int e = blockIdx.x * blockDim.x + threadIdx.x;
    if (e >= EHALF) return;
    int a = nbr[2 * e], b = nbr[2 * e + 1];
    float dx = xyz[3 * b + 0] - xyz[3 * a + 0];
    float dy = xyz[3 * b + 1] - xyz[3 * a + 1];
    float dz = xyz[3 * b + 2] - xyz[3 * a + 2];
    float d = sqrtf(dx * dx + dy * dy + dz * dz + 3e-15f);
    float o[17];
    rbf_env(d, 5.0f, o);
    #pragma unroll
    for (int k = 0; k < 17; k++) g_eemb[(size_t)e * 17 + k] = o[k];
}

__global__ void k_aemb(const int* __restrict__ map, const float* __restrict__ xyz,
                       const float* __restrict__ cg_xyz) {
    int a = blockIdx.x * blockDim.x + threadIdx.x;
    if (a >= NATOMS) return;
    int m = map[a];
    float dx = xyz[3 * a + 0] - cg_xyz[3 * m + 0];
    float dy = xyz[3 * a + 1] - cg_xyz[3 * m + 1];
    float dz = xyz[3 * a + 2] - cg_xyz[3 * m + 2];
    float d = sqrtf(dx * dx + dy * dy + dz * dz + 3e-15f);
    float o[17];
    rbf_env(d, 20.0f, o);
    #pragma unroll
    for (int k = 0; k < 17; k++) g_aemb[(size_t)a * 17 + k] = o[k];
}

// ---------------- SGEMM: C[n,128] = A[n,128] @ W[128, ldw][:, :128] + bias ----
// 256 threads, 64-row x 128-col tile, thread micro-tile 8x4, BK=32.
__global__ void k_gemm(const float* __restrict__ A, const float* __restrict__ W,
                       int ldw, const float* __restrict__ bias,
                       float* __restrict__ C, int n, int dosilu) {
    __shared__ float As[32 * 68];   // transposed A tile [kk][row], padded
    __shared__ float Ws[32 * 128];  // W tile [kk][col]
    int tid = threadIdx.x;
    int tx = tid & 31, ty = tid >> 5;
    int row0 = blockIdx.x * 64;
    float acc[8][4];
    #pragma unroll
    for (int i = 0; i < 8; i++)
        #pragma unroll
        for (int j = 0; j < 4; j++) acc[i][j] = 0.f;

    for (int k0 = 0; k0 < 128; k0 += 32) {
        #pragma unroll
        for (int j = 0; j < 2; j++) {
            int q = tid + j * 256;
            int r = q >> 3, c4 = q & 7;
            float4 v = make_float4(0.f, 0.f, 0.f, 0.f);
            if (row0 + r < n)
                v = *(const float4*)(A + (size_t)(row0 + r) * 128 + k0 + c4 * 4);
            As[(c4 * 4 + 0) * 68 + r] = v.x;
            As[(c4 * 4 + 1) * 68 + r] = v.y;
            As[(c4 * 4 + 2) * 68 + r] = v.z;
            As[(c4 * 4 + 3) * 68 + r] = v.w;
        }
        #pragma unroll
        for (int j = 0; j < 4; j++) {
            int q = tid + j * 256;
            int kk = q >> 5, c4 = q & 31;
            *(float4*)(Ws + kk * 128 + c4 * 4) =
                *(const float4*)(W + (size_t)(k0 + kk) * ldw + c4 * 4);
        }
        __syncthreads();
        #pragma unroll
        for (int kk = 0; kk < 32; kk++) {
            float4 a0 = *(const float4*)(As + kk * 68 + ty * 8);
            float4 a1 = *(const float4*)(As + kk * 68 + ty * 8 + 4);
            float4 b  = *(const float4*)(Ws + kk * 128 + tx * 4);
            float av[8] = {a0.x, a0.y, a0.z, a0.w, a1.x, a1.y, a1.z, a1.w};
            float bv[4] = {b.x, b.y, b.z, b.w};
            #pragma unroll
            for (int i = 0; i < 8; i++)
                #pragma unroll
                for (int j = 0; j < 4; j++)
                    acc[i][j] += av[i] * bv[j];
        }
        __syncthreads();
    }

    float4 bq = *(const float4*)(bias + tx * 4);
    float bb[4] = {bq.x, bq.y, bq.z, bq.w};
    #pragma unroll
    for (int i = 0; i < 8; i++) {
        int r = row0 + ty * 8 + i;
        if (r < n) {
            float o[4];
            #pragma unroll
            for (int j = 0; j < 4; j++) {
                float x = acc[i][j] + bb[j];
                if (dosilu) x = x / (1.0f + __expf(-x));
                o[j] = x;
            }
            *(float4*)(C + (size_t)r * 128 + tx * 4) =
                make_float4(o[0], o[1], o[2], o[3]);
        }
    }
}

// ---------------- edge message pass: h[a] += emb*phi[b]; h[b] += emb*phi[a] ---
__global__ void k_edge_conv(const int* __restrict__ nbr,
                            const float* __restrict__ Wd,   // (16, 384) use cols<128
                            const float* __restrict__ bd) { // (384)     use <128
    __shared__ float sW[16 * 128];
    __shared__ float sb[128];
    for (int t = threadIdx.x; t < 16 * 128; t += blockDim.x)
        sW[t] = Wd[(t >> 7) * 384 + (t & 127)];
    if (threadIdx.x < 128) sb[threadIdx.x] = bd[threadIdx.x];
    __syncthreads();

    int lane = threadIdx.x & 31;
    int w  = (blockIdx.x * blockDim.x + threadIdx.x) >> 5;
    int nw = (gridDim.x * blockDim.x) >> 5;
    float4 bv = *(const float4*)(sb + lane * 4);

    for (int e = w; e < EHALF; e += nw) {
        float rv = (lane < 17) ? g_eemb[(size_t)e * 17 + lane] : 0.f;
        float env = __shfl_sync(0xffffffffu, rv, 16);
        if (env == 0.f) continue;   // uniform across warp
        int a = nbr[2 * e], b = nbr[2 * e + 1];
        float ex = env * bv.x, ey = env * bv.y, ez = env * bv.z, ew = env * bv.w;
        #pragma unroll
        for (int k = 0; k < 16; k++) {
            float r = __shfl_sync(0xffffffffu, rv, k);
            float4 wv = *(const float4*)(sW + k * 128 + lane * 4);
            ex += r * wv.x; ey += r * wv.y; ez += r * wv.z; ew += r * wv.w;
        }
        float4 pb = *(const float4*)(g_phi + (size_t)b * FD + lane * 4);
        float4 pa = *(const float4*)(g_phi + (size_t)a * FD + lane * 4);
        red4(g_h + (size_t)a * FD + lane * 4, ex * pb.x, ey * pb.y, ez * pb.z, ew * pb.w);
        red4(g_h + (size_t)b * FD + lane * 4, ex * pa.x, ey * pa.y, ez * pa.z, ew * pa.w);
    }
}

// ---------------- CG pass: H[map[a]] += emb(d_iI)*phi[a] / cnt ---------------
__global__ void k_cg_conv(const int* __restrict__ map,
                          const float* __restrict__ Wd,
                          const float* __restrict__ bd) {
    __shared__ float sW[16 * 128];
    __shared__ float sb[128];
    for (int t = threadIdx.x; t < 16 * 128; t += blockDim.x)
        sW[t] = Wd[(t >> 7) * 384 + (t & 127)];
    if (threadIdx.x < 128) sb[threadIdx.x] = bd[threadIdx.x];
    __syncthreads();

    int lane = threadIdx.x & 31;
    int w  = (blockIdx.x * blockDim.x + threadIdx.x) >> 5;
    int nw = (gridDim.x * blockDim.x) >> 5;
    float4 bv = *(const float4*)(sb + lane * 4);

    for (int a = w; a < NATOMS; a += nw) {
        float rv = (lane < 17) ? g_aemb[(size_t)a * 17 + lane] : 0.f;
        float env = __shfl_sync(0xffffffffu, rv, 16);
        if (env == 0.f) continue;
        float ex = env * bv.x, ey = env * bv.y, ez = env * bv.z, ew = env * bv.w;
        #pragma unroll
        for (int k = 0; k < 16; k++) {
            float r = __shfl_sync(0xffffffffu, rv, k);
            float4 wv = *(const float4*)(sW + k * 128 + lane * 4);
            ex += r * wv.x; ey += r * wv.y; ez += r * wv.z; ew += r * wv.w;
        }
        float4 p = *(const float4*)(g_phi + (size_t)a * FD + lane * 4);
        int m = map[a];
        float ic = g_icnt[m];
        red4(g_H + (size_t)m * FD + lane * 4,
             ex * p.x * ic, ey * p.y * ic, ez * p.z * ic, ew * p.w * ic);
    }
}

// ---------------- H snapshot after conv0 message update ----------------------
__global__ void k_snapshot(const int* __restrict__ map) {
    int idx = blockIdx.x * blockDim.x + threadIdx.x;
    if (idx >= NATOMS * 32) return;
    int a = idx >> 5, c = idx & 31;
    int m = map[a];
    float ic = g_icnt[m];
    float4 v = *(const float4*)(g_h + (size_t)a * FD + c * 4);
    red4(g_H + (size_t)m * FD + c * 4, v.x * ic, v.y * ic, v.z * ic, v.w * ic);
}

// ---------------- output: [H (M,F), h (N,F)] ---------------------------------
__global__ void k_out(float* __restrict__ out) {
    int idx = blockIdx.x * blockDim.x + threadIdx.x;
    const int nH = MBEADS * FD / 4;
    const int tot = nH + NATOMS * FD / 4;
    if (idx >= tot) return;
    float4 v;
    if (idx < nH) v = ((const float4*)g_H)[idx];
    else          v = ((const float4*)g_h)[idx - nH];
    ((float4*)out)[idx] = v;
}

// ---------------- launch ------------------------------------------------------
extern "C" void kernel_launch(void* const* d_in, const int* in_sizes, int n_in,
                              void* d_out, int out_size) {
    const int*   z        = (const int*)d_in[0];
    const float* xyz      = (const float*)d_in[1];
    const int*   cg_z     = (const int*)d_in[2];
    const float* cg_xyz   = (const float*)d_in[3];
    const int*   mapping  = (const int*)d_in[4];
    const int*   nbr      = (const int*)d_in[5];
    // d_in[6] cg_nbr_list, d_in[7] ic: unused (dead in reference output)
    const float* emb_atom = (const float*)d_in[8];
    const float* emb_res  = (const float*)d_in[9];
    const float* Wm1 = (const float*)d_in[10];
    const float* bm1 = (const float*)d_in[11];
    const float* Wm2 = (const float*)d_in[12];
    const float* bm2 = (const float*)d_in[13];
    const float* Wdm = (const float*)d_in[14];
    const float* bdm = (const float*)d_in[15];
    const float* Wc1 = (const float*)d_in[16];
    const float* bc1 = (const float*)d_in[17];
    const float* Wc2 = (const float*)d_in[18];
    const float* bc2 = (const float*)d_in[19];
    const float* Wdc = (const float*)d_in[20];
    const float* bdc = (const float*)d_in[21];

    float *ph = nullptr, *phid = nullptr, *pphi = nullptr;
    cudaGetSymbolAddress((void**)&ph, g_h);
    cudaGetSymbolAddress((void**)&phid, g_hid);
    cudaGetSymbolAddress((void**)&pphi, g_phi);

    k_zero<<<(MBEADS * FD + 255) / 256, 256>>>();
    k_init<<<(NATOMS * 32 + 255) / 256, 256>>>(z, cg_z, mapping, emb_atom, emb_res);
    k_icnt<<<(MBEADS + 255) / 256, 256>>>();
    k_epre<<<(EHALF + 255) / 256, 256>>>(nbr, xyz);
    k_aemb<<<(NATOMS + 255) / 256, 256>>>(mapping, xyz, cg_xyz);

    const int gb = (NATOMS + 63) / 64;
    for (int i = 0; i < 2; i++) {
        // message block: phi = silu(h@Wm1+bm1)@Wm2[:, :F]+bm2[:F]
        k_gemm<<<gb, 256>>>(ph,   Wm1 + (size_t)i * 128 * 128, 128, bm1 + i * 128, phid, NATOMS, 1);
        k_gemm<<<gb, 256>>>(phid, Wm2 + (size_t)i * 128 * 384, 384, bm2 + i * 384, pphi, NATOMS, 0);
        k_edge_conv<<<592, 256>>>(nbr, Wdm + (size_t)i * 16 * 384, bdm + i * 384);
        if (i == 0)
            k_snapshot<<<(NATOMS * 32 + 255) / 256, 256>>>(mapping);
        // CG block: only s0 feeds H
        k_gemm<<<gb, 256>>>(ph,   Wc1 + (size_t)i * 128 * 128, 128, bc1 + i * 128, phid, NATOMS, 1);
        k_gemm<<<gb, 256>>>(phid, Wc2 + (size_t)i * 128 * 384, 384, bc2 + i * 384, pphi, NATOMS, 0);
        k_cg_conv<<<592, 256>>>(mapping, Wdc + (size_t)i * 16 * 384, bdc + i * 384);
    }
    k_out<<<((MBEADS + NATOMS) * 32 + 255) / 256, 256>>>((float*)d_out);
}

// round 13
// speedup vs baseline: 1.0045x; 1.0001x over previous
#include <cuda_runtime.h>
#include <math.h>

#define NATOMS 20000
#define MBEADS 2000
#define EHALF  160000
#define FD     128
#define NRBF   16
#define PIF    3.14159265358979323846f

// ---------------- scratch (device globals; no allocation allowed) -------------
__device__ float g_h[NATOMS * FD];      // node features (updated in place)
__device__ float g_hid[NATOMS * FD];    // silu hidden
__device__ float g_phi[NATOMS * FD];    // phi (first F columns only)
__device__ float g_H[MBEADS * FD];      // bead accumulator
__device__ float g_cnt[MBEADS];
__device__ float g_icnt[MBEADS];
__device__ float g_eemb[EHALF * 17];    // per-edge: rbf*env (16) + env
__device__ float g_aemb[NATOMS * 17];   // per-atom (CG cutoff): rbf*env (16) + env

// vectorized global reduction (sm_90+)
__device__ __forceinline__ void red4(float* addr, float x, float y, float z, float w) {
    asm volatile("red.global.add.v4.f32 [%0], {%1,%2,%3,%4};"
                 :: "l"(addr), "f"(x), "f"(y), "f"(z), "f"(w) : "memory");
}

// ---------------- init / precompute ----------------
__global__ void k_zero() {
    int i = blockIdx.x * blockDim.x + threadIdx.x;
    if (i < MBEADS * FD) g_H[i] = 0.f;
    if (i < MBEADS) g_cnt[i] = 0.f;
}

__global__ void k_init(const int* __restrict__ z, const int* __restrict__ cg_z,
                       const int* __restrict__ map,
                       const float* __restrict__ emb_atom,
                       const float* __restrict__ emb_res) {
    int idx = blockIdx.x * blockDim.x + threadIdx.x;
    if (idx >= NATOMS * 32) return;
    int a = idx >> 5, c = idx & 31;
    int f = c * 4;
    float4 v;
    if (f < 64) v = *(const float4*)(emb_atom + (size_t)z[a] * 64 + f);
    else        v = *(const float4*)(emb_res + (size_t)cg_z[map[a]] * 64 + (f - 64));
    *(float4*)(g_h + (size_t)a * FD + f) = v;
    if (c == 0) atomicAdd(&g_cnt[map[a]], 1.0f);
}

__global__ void k_icnt() {
    int m = blockIdx.x * blockDim.x + threadIdx.x;
    if (m < MBEADS) g_icnt[m] = 1.0f / fmaxf(g_cnt[m], 1.0f);
}

__device__ __forceinline__ void rbf_env(float d, float cut, float* out17) {
    float env = 0.f;
    if (d < cut) env = 0.5f * (cosf(PIF * d / cut) + 1.0f);
    if (env == 0.f) {
        #pragma unroll
        for (int k = 0; k < 17; k++) out17[k] = 0.f;
        return;
    }
    float invd = 1.0f / d;
    float w = PIF / cut * d;
    #pragma unroll
    for (int k = 0; k < 16; k++)
        out17[k] = env * sinf((float)(k + 1) * w) * invd;
    out17[16] = env;
}

__global__ void k_epre(const int* __restrict__ nbr, const float* __restrict__ xyz) {
    int e = blockIdx.x * blockDim.x + threadIdx.x;
    if (e >= EHALF) return;
    int a = nbr[2 * e], b = nbr[2 * e + 1];
    float dx = xyz[3 * b + 0] - xyz[3 * a + 0];
    float dy = xyz[3 * b + 1] - xyz[3 * a + 1];
    float dz = xyz[3 * b + 2] - xyz[3 * a + 2];
    float d = sqrtf(dx * dx + dy * dy + dz * dz + 3e-15f);
    float o[17];
    rbf_env(d, 5.0f, o);
    #pragma unroll
    for (int k = 0; k < 17; k++) g_eemb[(size_t)e * 17 + k] = o[k];
}

__global__ void k_aemb(const int* __restrict__ map, const float* __restrict__ xyz,
                       const float* __restrict__ cg_xyz) {
    int a = blockIdx.x * blockDim.x + threadIdx.x;
    if (a >= NATOMS) return;
    int m = map[a];
    float dx = xyz[3 * a + 0] - cg_xyz[3 * m + 0];
    float dy = xyz[3 * a + 1] - cg_xyz[3 * m + 1];
    float dz = xyz[3 * a + 2] - cg_xyz[3 * m + 2];
    float d = sqrtf(dx * dx + dy * dy + dz * dz + 3e-15f);
    float o[17];
    rbf_env(d, 20.0f, o);
    #pragma unroll
    for (int k = 0; k < 17; k++) g_aemb[(size_t)a * 17 + k] = o[k];
}

// ---------------- SGEMM: C[n,128] = A[n,128] @ W[128, ldw][:, :128] + bias ----
// 256 threads, 64-row x 128-col tile, thread micro-tile 8x4, BK=32.
__global__ void k_gemm(const float* __restrict__ A, const float* __restrict__ W,
                       int ldw, const float* __restrict__ bias,
                       float* __restrict__ C, int n, int dosilu) {
    __shared__ float As[32 * 68];   // transposed A tile [kk][row], padded
    __shared__ float Ws[32 * 128];  // W tile [kk][col]
    int tid = threadIdx.x;
    int tx = tid & 31, ty = tid >> 5;
    int row0 = blockIdx.x * 64;
    float acc[8][4];
    #pragma unroll
    for (int i = 0; i < 8; i++)
        #pragma unroll
        for (int j = 0; j < 4; j++) acc[i][j] = 0.f;

    for (int k0 = 0; k0 < 128; k0 += 32) {
        #pragma unroll
        for (int j = 0; j < 2; j++) {
            int q = tid + j * 256;
            int r = q >> 3, c4 = q & 7;
            float4 v = make_float4(0.f, 0.f, 0.f, 0.f);
            if (row0 + r < n)
                v = *(const float4*)(A + (size_t)(row0 + r) * 128 + k0 + c4 * 4);
            As[(c4 * 4 + 0) * 68 + r] = v.x;
            As[(c4 * 4 + 1) * 68 + r] = v.y;
            As[(c4 * 4 + 2) * 68 + r] = v.z;
            As[(c4 * 4 + 3) * 68 + r] = v.w;
        }
        #pragma unroll
        for (int j = 0; j < 4; j++) {
            int q = tid + j * 256;
            int kk = q >> 5, c4 = q & 31;
            *(float4*)(Ws + kk * 128 + c4 * 4) =
                *(const float4*)(W + (size_t)(k0 + kk) * ldw + c4 * 4);
        }
        __syncthreads();
        #pragma unroll
        for (int kk = 0; kk < 32; kk++) {
            float4 a0 = *(const float4*)(As + kk * 68 + ty * 8);
            float4 a1 = *(const float4*)(As + kk * 68 + ty * 8 + 4);
            float4 b  = *(const float4*)(Ws + kk * 128 + tx * 4);
            float av[8] = {a0.x, a0.y, a0.z, a0.w, a1.x, a1.y, a1.z, a1.w};
            float bv[4] = {b.x, b.y, b.z, b.w};
            #pragma unroll
            for (int i = 0; i < 8; i++)
                #pragma unroll
                for (int j = 0; j < 4; j++)
                    acc[i][j] += av[i] * bv[j];
        }
        __syncthreads();
    }

    float4 bq = *(const float4*)(bias + tx * 4);
    float bb[4] = {bq.x, bq.y, bq.z, bq.w};
    #pragma unroll
    for (int i = 0; i < 8; i++) {
        int r = row0 + ty * 8 + i;
        if (r < n) {
            float o[4];
            #pragma unroll
            for (int j = 0; j < 4; j++) {
                float x = acc[i][j] + bb[j];
                if (dosilu) x = x / (1.0f + __expf(-x));
                o[j] = x;
            }
            *(float4*)(C + (size_t)r * 128 + tx * 4) =
                make_float4(o[0], o[1], o[2], o[3]);
        }
    }
}

// ---------------- edge message pass: h[a] += emb*phi[b]; h[b] += emb*phi[a] ---
__global__ void k_edge_conv(const int* __restrict__ nbr,
                            const float* __restrict__ Wd,   // (16, 384) use cols<128
                            const float* __restrict__ bd) { // (384)     use <128
    __shared__ float sW[16 * 128];
    __shared__ float sb[128];
    for (int t = threadIdx.x; t < 16 * 128; t += blockDim.x)
        sW[t] = Wd[(t >> 7) * 384 + (t & 127)];
    if (threadIdx.x < 128) sb[threadIdx.x] = bd[threadIdx.x];
    __syncthreads();

    int lane = threadIdx.x & 31;
    int w  = (blockIdx.x * blockDim.x + threadIdx.x) >> 5;
    int nw = (gridDim.x * blockDim.x) >> 5;
    float4 bv = *(const float4*)(sb + lane * 4);

    for (int e = w; e < EHALF; e += nw) {
        float rv = (lane < 17) ? g_eemb[(size_t)e * 17 + lane] : 0.f;
        float env = __shfl_sync(0xffffffffu, rv, 16);
        if (env == 0.f) continue;   // uniform across warp
        int a = nbr[2 * e], b = nbr[2 * e + 1];
        float ex = env * bv.x, ey = env * bv.y, ez = env * bv.z, ew = env * bv.w;
        #pragma unroll
        for (int k = 0; k < 16; k++) {
            float r = __shfl_sync(0xffffffffu, rv, k);
            float4 wv = *(const float4*)(sW + k * 128 + lane * 4);
            ex += r * wv.x; ey += r * wv.y; ez += r * wv.z; ew += r * wv.w;
        }
        float4 pb = *(const float4*)(g_phi + (size_t)b * FD + lane * 4);
        float4 pa = *(const float4*)(g_phi + (size_t)a * FD + lane * 4);
        red4(g_h + (size_t)a * FD + lane * 4, ex * pb.x, ey * pb.y, ez * pb.z, ew * pb.w);
        red4(g_h + (size_t)b * FD + lane * 4, ex * pa.x, ey * pa.y, ez * pa.z, ew * pa.w);
    }
}

// ---------------- CG pass: H[map[a]] += emb(d_iI)*phi[a] / cnt ---------------
__global__ void k_cg_conv(const int* __restrict__ map,
                          const float* __restrict__ Wd,
                          const float* __restrict__ bd) {
    __shared__ float sW[16 * 128];
    __shared__ float sb[128];
    for (int t = threadIdx.x; t < 16 * 128; t += blockDim.x)
        sW[t] = Wd[(t >> 7) * 384 + (t & 127)];
    if (threadIdx.x < 128) sb[threadIdx.x] = bd[threadIdx.x];
    __syncthreads();

    int lane = threadIdx.x & 31;
    int w  = (blockIdx.x * blockDim.x + threadIdx.x) >> 5;
    int nw = (gridDim.x * blockDim.x) >> 5;
    float4 bv = *(const float4*)(sb + lane * 4);

    for (int a = w; a < NATOMS; a += nw) {
        float rv = (lane < 17) ? g_aemb[(size_t)a * 17 + lane] : 0.f;
        float env = __shfl_sync(0xffffffffu, rv, 16);
        if (env == 0.f) continue;
        float ex = env * bv.x, ey = env * bv.y, ez = env * bv.z, ew = env * bv.w;
        #pragma unroll
        for (int k = 0; k < 16; k++) {
            float r = __shfl_sync(0xffffffffu, rv, k);
            float4 wv = *(const float4*)(sW + k * 128 + lane * 4);
            ex += r * wv.x; ey += r * wv.y; ez += r * wv.z; ew += r * wv.w;
        }
        float4 p = *(const float4*)(g_phi + (size_t)a * FD + lane * 4);
        int m = map[a];
        float ic = g_icnt[m];
        red4(g_H + (size_t)m * FD + lane * 4,
             ex * p.x * ic, ey * p.y * ic, ez * p.z * ic, ew * p.w * ic);
    }
}

// ---------------- H snapshot after conv0 message update ----------------------
__global__ void k_snapshot(const int* __restrict__ map) {
    int idx = blockIdx.x * blockDim.x + threadIdx.x;
    if (idx >= NATOMS * 32) return;
    int a = idx >> 5, c = idx & 31;
    int m = map[a];
    float ic = g_icnt[m];
    float4 v = *(const float4*)(g_h + (size_t)a * FD + c * 4);
    red4(g_H + (size_t)m * FD + c * 4, v.x * ic, v.y * ic, v.z * ic, v.w * ic);
}

// ---------------- output: [H (M,F), h (N,F)] ---------------------------------
__global__ void k_out(float* __restrict__ out) {
    int idx = blockIdx.x * blockDim.x + threadIdx.x;
    const int nH = MBEADS * FD / 4;
    const int tot = nH + NATOMS * FD / 4;
    if (idx >= tot) return;
    float4 v;
    if (idx < nH) v = ((const float4*)g_H)[idx];
    else          v = ((const float4*)g_h)[idx - nH];
    ((float4*)out)[idx] = v;
}

// ---------------- launch ------------------------------------------------------
extern "C" void kernel_launch(void* const* d_in, const int* in_sizes, int n_in,
                              void* d_out, int out_size) {
    const int*   z        = (const int*)d_in[0];
    const float* xyz      = (const float*)d_in[1];
    const int*   cg_z     = (const int*)d_in[2];
    const float* cg_xyz   = (const float*)d_in[3];
    const int*   mapping  = (const int*)d_in[4];
    const int*   nbr      = (const int*)d_in[5];
    // d_in[6] cg_nbr_list, d_in[7] ic: unused (dead in reference output)
    const float* emb_atom = (const float*)d_in[8];
    const float* emb_res  = (const float*)d_in[9];
    const float* Wm1 = (const float*)d_in[10];
    const float* bm1 = (const float*)d_in[11];
    const float* Wm2 = (const float*)d_in[12];
    const float* bm2 = (const float*)d_in[13];
    const float* Wdm = (const float*)d_in[14];
    const float* bdm = (const float*)d_in[15];
    const float* Wc1 = (const float*)d_in[16];
    const float* bc1 = (const float*)d_in[17];
    const float* Wc2 = (const float*)d_in[18];
    const float* bc2 = (const float*)d_in[19];
    const float* Wdc = (const float*)d_in[20];
    const float* bdc = (const float*)d_in[21];

    float *ph = nullptr, *phid = nullptr, *pphi = nullptr;
    cudaGetSymbolAddress((void**)&ph, g_h);
    cudaGetSymbolAddress((void**)&phid, g_hid);
    cudaGetSymbolAddress((void**)&pphi, g_phi);

    k_zero<<<(MBEADS * FD + 255) / 256, 256>>>();
    k_init<<<(NATOMS * 32 + 255) / 256, 256>>>(z, cg_z, mapping, emb_atom, emb_res);
    k_icnt<<<(MBEADS + 255) / 256, 256>>>();
    k_epre<<<(EHALF + 255) / 256, 256>>>(nbr, xyz);
    k_aemb<<<(NATOMS + 255) / 256, 256>>>(mapping, xyz, cg_xyz);

    const int gb = (NATOMS + 63) / 64;
    for (int i = 0; i < 2; i++) {
        // message block: phi = silu(h@Wm1+bm1)@Wm2[:, :F]+bm2[:F]
        k_gemm<<<gb, 256>>>(ph,   Wm1 + (size_t)i * 128 * 128, 128, bm1 + i * 128, phid, NATOMS, 1);
        k_gemm<<<gb, 256>>>(phid, Wm2 + (size_t)i * 128 * 384, 384, bm2 + i * 384, pphi, NATOMS, 0);
        k_edge_conv<<<592, 256>>>(nbr, Wdm + (size_t)i * 16 * 384, bdm + i * 384);
        if (i == 0)
            k_snapshot<<<(NATOMS * 32 + 255) / 256, 256>>>(mapping);
        // CG block: only s0 feeds H
        k_gemm<<<gb, 256>>>(ph,   Wc1 + (size_t)i * 128 * 128, 128, bc1 + i * 128, phid, NATOMS, 1);
        k_gemm<<<gb, 256>>>(phid, Wc2 + (size_t)i * 128 * 384, 384, bc2 + i * 384, pphi, NATOMS, 0);
        k_cg_conv<<<592, 256>>>(mapping, Wdc + (size_t)i * 16 * 384, bdc + i * 384);
    }
    k_out<<<((MBEADS + NATOMS) * 32 + 255) / 256, 256>>>((float*)d_out);
}

// round 14
// speedup vs baseline: 1.0096x; 1.0051x over previous
#include <cuda_runtime.h>
#include <math.h>

#define NATOMS 20000
#define MBEADS 2000
#define EHALF  160000
#define FD     128
#define NRBF   16
#define PIF    3.14159265358979323846f

// ---------------- scratch (device globals; no allocation allowed) -------------
__device__ float g_h[NATOMS * FD];      // node features (updated in place)
__device__ float g_hid[NATOMS * FD];    // silu hidden
__device__ float g_phi[NATOMS * FD];    // phi (first F columns only)
__device__ float g_H[MBEADS * FD];      // bead accumulator
__device__ float g_cnt[MBEADS];
__device__ float g_icnt[MBEADS];
__device__ float g_eemb[EHALF * 17];    // per-edge: rbf*env (16) + env
__device__ float g_aemb[NATOMS * 17];   // per-atom (CG cutoff): rbf*env (16) + env

// vectorized global reduction (sm_90+)
__device__ __forceinline__ void red4(float* addr, float x, float y, float z, float w) {
    asm volatile("red.global.add.v4.f32 [%0], {%1,%2,%3,%4};"
                 :: "l"(addr), "f"(x), "f"(y), "f"(z), "f"(w) : "memory");
}

// ---------------- init / precompute ----------------
__global__ void k_zero() {
    int i = blockIdx.x * blockDim.x + threadIdx.x;
    if (i < MBEADS * FD) g_H[i] = 0.f;
    if (i < MBEADS) g_cnt[i] = 0.f;
}

__global__ void k_init(const int* __restrict__ z, const int* __restrict__ cg_z,
                       const int* __restrict__ map,
                       const float* __restrict__ emb_atom,
                       const float* __restrict__ emb_res) {
    int idx = blockIdx.x * blockDim.x + threadIdx.x;
    if (idx >= NATOMS * 32) return;
    int a = idx >> 5, c = idx & 31;
    int f = c * 4;
    float4 v;
    if (f < 64) v = *(const float4*)(emb_atom + (size_t)z[a] * 64 + f);
    else        v = *(const float4*)(emb_res + (size_t)cg_z[map[a]] * 64 + (f - 64));
    *(float4*)(g_h + (size_t)a * FD + f) = v;
    if (c == 0) atomicAdd(&g_cnt[map[a]], 1.0f);
}

__global__ void k_icnt() {
    int m = blockIdx.x * blockDim.x + threadIdx.x;
    if (m < MBEADS) g_icnt[m] = 1.0f / fmaxf(g_cnt[m], 1.0f);
}

__device__ __forceinline__ void rbf_env(float d, float cut, float* out17) {
    float env = 0.f;
    if (d < cut) env = 0.5f * (cosf(PIF * d / cut) + 1.0f);
    if (env == 0.f) {
        #pragma unroll
        for (int k = 0; k < 17; k++) out17[k] = 0.f;
        return;
    }
    float invd = 1.0f / d;
    float w = PIF / cut * d;
    #pragma unroll
    for (int k = 0; k < 16; k++)
        out17[k] = env * sinf((float)(k + 1) * w) * invd;
    out17[16] = env;
}

__global__ void k_epre(const int* __restrict__ nbr, const float* __restrict__ xyz) {
    int e = blockIdx.x * blockDim.x + threadIdx.x;
    if (e >= EHALF) return;
    int a = nbr[2 * e], b = nbr[2 * e + 1];
    float dx = xyz[3 * b + 0] - xyz[3 * a + 0];
    float dy = xyz[3 * b + 1] - xyz[3 * a + 1];
    float dz = xyz[3 * b + 2] - xyz[3 * a + 2];
    float d = sqrtf(dx * dx + dy * dy + dz * dz + 3e-15f);
    float o[17];
    rbf_env(d, 5.0f, o);
    #pragma unroll
    for (int k = 0; k < 17; k++) g_eemb[(size_t)e * 17 + k] = o[k];
}

__global__ void k_aemb(const int* __restrict__ map, const float* __restrict__ xyz,
                       const float* __restrict__ cg_xyz) {
    int a = blockIdx.x * blockDim.x + threadIdx.x;
    if (a >= NATOMS) return;
    int m = map[a];
    float dx = xyz[3 * a + 0] - cg_xyz[3 * m + 0];
    float dy = xyz[3 * a + 1] - cg_xyz[3 * m + 1];
    float dz = xyz[3 * a + 2] - cg_xyz[3 * m + 2];
    float d = sqrtf(dx * dx + dy * dy + dz * dz + 3e-15f);
    float o[17];
    rbf_env(d, 20.0f, o);
    #pragma unroll
    for (int k = 0; k < 17; k++) g_aemb[(size_t)a * 17 + k] = o[k];
}

// ---------------- SGEMM: C[n,128] = A[n,128] @ W[128, ldw][:, :128] + bias ----
// 256 threads, 64-row x 128-col tile, thread micro-tile 8x4, BK=32.
__global__ void k_gemm(const float* __restrict__ A, const float* __restrict__ W,
                       int ldw, const float* __restrict__ bias,
                       float* __restrict__ C, int n, int dosilu) {
    __shared__ float As[32 * 68];   // transposed A tile [kk][row], padded
    __shared__ float Ws[32 * 128];  // W tile [kk][col]
    int tid = threadIdx.x;
    int tx = tid & 31, ty = tid >> 5;
    int row0 = blockIdx.x * 64;
    float acc[8][4];
    #pragma unroll
    for (int i = 0; i < 8; i++)
        #pragma unroll
        for (int j = 0; j < 4; j++) acc[i][j] = 0.f;

    for (int k0 = 0; k0 < 128; k0 += 32) {
        #pragma unroll
        for (int j = 0; j < 2; j++) {
            int q = tid + j * 256;
            int r = q >> 3, c4 = q & 7;
            float4 v = make_float4(0.f, 0.f, 0.f, 0.f);
            if (row0 + r < n)
                v = *(const float4*)(A + (size_t)(row0 + r) * 128 + k0 + c4 * 4);
            As[(c4 * 4 + 0) * 68 + r] = v.x;
            As[(c4 * 4 + 1) * 68 + r] = v.y;
            As[(c4 * 4 + 2) * 68 + r] = v.z;
            As[(c4 * 4 + 3) * 68 + r] = v.w;
        }
        #pragma unroll
        for (int j = 0; j < 4; j++) {
            int q = tid + j * 256;
            int kk = q >> 5, c4 = q & 31;
            *(float4*)(Ws + kk * 128 + c4 * 4) =
                *(const float4*)(W + (size_t)(k0 + kk) * ldw + c4 * 4);
        }
        __syncthreads();
        #pragma unroll
        for (int kk = 0; kk < 32; kk++) {
            float4 a0 = *(const float4*)(As + kk * 68 + ty * 8);
            float4 a1 = *(const float4*)(As + kk * 68 + ty * 8 + 4);
            float4 b  = *(const float4*)(Ws + kk * 128 + tx * 4);
            float av[8] = {a0.x, a0.y, a0.z, a0.w, a1.x, a1.y, a1.z, a1.w};
            float bv[4] = {b.x, b.y, b.z, b.w};
            #pragma unroll
            for (int i = 0; i < 8; i++)
                #pragma unroll
                for (int j = 0; j < 4; j++)
                    acc[i][j] += av[i] * bv[j];
        }
        __syncthreads();
    }

    float4 bq = *(const float4*)(bias + tx * 4);
    float bb[4] = {bq.x, bq.y, bq.z, bq.w};
    #pragma unroll
    for (int i = 0; i < 8; i++) {
        int r = row0 + ty * 8 + i;
        if (r < n) {
            float o[4];
            #pragma unroll
            for (int j = 0; j < 4; j++) {
                float x = acc[i][j] + bb[j];
                if (dosilu) x = x / (1.0f + __expf(-x));
                o[j] = x;
            }
            *(float4*)(C + (size_t)r * 128 + tx * 4) =
                make_float4(o[0], o[1], o[2], o[3]);
        }
    }
}

// ---------------- edge message pass: h[a] += emb*phi[b]; h[b] += emb*phi[a] ---
__global__ void k_edge_conv(const int* __restrict__ nbr,
                            const float* __restrict__ Wd,   // (16, 384) use cols<128
                            const float* __restrict__ bd) { // (384)     use <128
    __shared__ float sW[16 * 128];
    __shared__ float sb[128];
    for (int t = threadIdx.x; t < 16 * 128; t += blockDim.x)
        sW[t] = Wd[(t >> 7) * 384 + (t & 127)];
    if (threadIdx.x < 128) sb[threadIdx.x] = bd[threadIdx.x];
    __syncthreads();

    int lane = threadIdx.x & 31;
    int w  = (blockIdx.x * blockDim.x + threadIdx.x) >> 5;
    int nw = (gridDim.x * blockDim.x) >> 5;
    float4 bv = *(const float4*)(sb + lane * 4);

    for (int e = w; e < EHALF; e += nw) {
        float rv = (lane < 17) ? g_eemb[(size_t)e * 17 + lane] : 0.f;
        float env = __shfl_sync(0xffffffffu, rv, 16);
        if (env == 0.f) continue;   // uniform across warp
        int a = nbr[2 * e], b = nbr[2 * e + 1];
        float ex = env * bv.x, ey = env * bv.y, ez = env * bv.z, ew = env * bv.w;
        #pragma unroll
        for (int k = 0; k < 16; k++) {
            float r = __shfl_sync(0xffffffffu, rv, k);
            float4 wv = *(const float4*)(sW + k * 128 + lane * 4);
            ex += r * wv.x; ey += r * wv.y; ez += r * wv.z; ew += r * wv.w;
        }
        float4 pb = *(const float4*)(g_phi + (size_t)b * FD + lane * 4);
        float4 pa = *(const float4*)(g_phi + (size_t)a * FD + lane * 4);
        red4(g_h + (size_t)a * FD + lane * 4, ex * pb.x, ey * pb.y, ez * pb.z, ew * pb.w);
        red4(g_h + (size_t)b * FD + lane * 4, ex * pa.x, ey * pa.y, ez * pa.z, ew * pa.w);
    }
}

// ---------------- CG pass: H[map[a]] += emb(d_iI)*phi[a] / cnt ---------------
__global__ void k_cg_conv(const int* __restrict__ map,
                          const float* __restrict__ Wd,
                          const float* __restrict__ bd) {
    __shared__ float sW[16 * 128];
    __shared__ float sb[128];
    for (int t = threadIdx.x; t < 16 * 128; t += blockDim.x)
        sW[t] = Wd[(t >> 7) * 384 + (t & 127)];
    if (threadIdx.x < 128) sb[threadIdx.x] = bd[threadIdx.x];
    __syncthreads();

    int lane = threadIdx.x & 31;
    int w  = (blockIdx.x * blockDim.x + threadIdx.x) >> 5;
    int nw = (gridDim.x * blockDim.x) >> 5;
    float4 bv = *(const float4*)(sb + lane * 4);

    for (int a = w; a < NATOMS; a += nw) {
        float rv = (lane < 17) ? g_aemb[(size_t)a * 17 + lane] : 0.f;
        float env = __shfl_sync(0xffffffffu, rv, 16);
        if (env == 0.f) continue;
        float ex = env * bv.x, ey = env * bv.y, ez = env * bv.z, ew = env * bv.w;
        #pragma unroll
        for (int k = 0; k < 16; k++) {
            float r = __shfl_sync(0xffffffffu, rv, k);
            float4 wv = *(const float4*)(sW + k * 128 + lane * 4);
            ex += r * wv.x; ey += r * wv.y; ez += r * wv.z; ew += r * wv.w;
        }
        float4 p = *(const float4*)(g_phi + (size_t)a * FD + lane * 4);
        int m = map[a];
        float ic = g_icnt[m];
        red4(g_H + (size_t)m * FD + lane * 4,
             ex * p.x * ic, ey * p.y * ic, ez * p.z * ic, ew * p.w * ic);
    }
}

// ---------------- H snapshot after conv0 message update ----------------------
__global__ void k_snapshot(const int* __restrict__ map) {
    int idx = blockIdx.x * blockDim.x + threadIdx.x;
    if (idx >= NATOMS * 32) return;
    int a = idx >> 5, c = idx & 31;
    int m = map[a];
    float ic = g_icnt[m];
    float4 v = *(const float4*)(g_h + (size_t)a * FD + c * 4);
    red4(g_H + (size_t)m * FD + c * 4, v.x * ic, v.y * ic, v.z * ic, v.w * ic);
}

// ---------------- output: [H (M,F), h (N,F)] ---------------------------------
__global__ void k_out(float* __restrict__ out) {
    int idx = blockIdx.x * blockDim.x + threadIdx.x;
    const int nH = MBEADS * FD / 4;
    const int tot = nH + NATOMS * FD / 4;
    if (idx >= tot) return;
    float4 v;
    if (idx < nH) v = ((const float4*)g_H)[idx];
    else          v = ((const float4*)g_h)[idx - nH];
    ((float4*)out)[idx] = v;
}

// ---------------- launch ------------------------------------------------------
extern "C" void kernel_launch(void* const* d_in, const int* in_sizes, int n_in,
                              void* d_out, int out_size) {
    const int*   z        = (const int*)d_in[0];
    const float* xyz      = (const float*)d_in[1];
    const int*   cg_z     = (const int*)d_in[2];
    const float* cg_xyz   = (const float*)d_in[3];
    const int*   mapping  = (const int*)d_in[4];
    const int*   nbr      = (const int*)d_in[5];
    // d_in[6] cg_nbr_list, d_in[7] ic: unused (dead in reference output)
    const float* emb_atom = (const float*)d_in[8];
    const float* emb_res  = (const float*)d_in[9];
    const float* Wm1 = (const float*)d_in[10];
    const float* bm1 = (const float*)d_in[11];
    const float* Wm2 = (const float*)d_in[12];
    const float* bm2 = (const float*)d_in[13];
    const float* Wdm = (const float*)d_in[14];
    const float* bdm = (const float*)d_in[15];
    const float* Wc1 = (const float*)d_in[16];
    const float* bc1 = (const float*)d_in[17];
    const float* Wc2 = (const float*)d_in[18];
    const float* bc2 = (const float*)d_in[19];
    const float* Wdc = (const float*)d_in[20];
    const float* bdc = (const float*)d_in[21];

    float *ph = nullptr, *phid = nullptr, *pphi = nullptr;
    cudaGetSymbolAddress((void**)&ph, g_h);
    cudaGetSymbolAddress((void**)&phid, g_hid);
    cudaGetSymbolAddress((void**)&pphi, g_phi);

    k_zero<<<(MBEADS * FD + 255) / 256, 256>>>();
    k_init<<<(NATOMS * 32 + 255) / 256, 256>>>(z, cg_z, mapping, emb_atom, emb_res);
    k_icnt<<<(MBEADS + 255) / 256, 256>>>();
    k_epre<<<(EHALF + 255) / 256, 256>>>(nbr, xyz);
    k_aemb<<<(NATOMS + 255) / 256, 256>>>(mapping, xyz, cg_xyz);

    const int gb = (NATOMS + 63) / 64;
    for (int i = 0; i < 2; i++) {
        // message block: phi = silu(h@Wm1+bm1)@Wm2[:, :F]+bm2[:F]
        k_gemm<<<gb, 256>>>(ph,   Wm1 + (size_t)i * 128 * 128, 128, bm1 + i * 128, phid, NATOMS, 1);
        k_gemm<<<gb, 256>>>(phid, Wm2 + (size_t)i * 128 * 384, 384, bm2 + i * 384, pphi, NATOMS, 0);
        k_edge_conv<<<592, 256>>>(nbr, Wdm + (size_t)i * 16 * 384, bdm + i * 384);
        if (i == 0)
            k_snapshot<<<(NATOMS * 32 + 255) / 256, 256>>>(mapping);
        // CG block: only s0 feeds H
        k_gemm<<<gb, 256>>>(ph,   Wc1 + (size_t)i * 128 * 128, 128, bc1 + i * 128, phid, NATOMS, 1);
        k_gemm<<<gb, 256>>>(phid, Wc2 + (size_t)i * 128 * 384, 384, bc2 + i * 384, pphi, NATOMS, 0);
        k_cg_conv<<<592, 256>>>(mapping, Wdc + (size_t)i * 16 * 384, bdc + i * 384);
    }
    k_out<<<((MBEADS + NATOMS) * 32 + 255) / 256, 256>>>((float*)d_out);
}

// round 15
// speedup vs baseline: 1.0105x; 1.0008x over previous
#include <cuda_runtime.h>
#include <math.h>

#define NATOMS 20000
#define MBEADS 2000
#define EHALF  160000
#define FD     128
#define NRBF   16
#define PIF    3.14159265358979323846f

// ---------------- scratch (device globals; no allocation allowed) -------------
__device__ float g_h[NATOMS * FD];      // node features (updated in place)
__device__ float g_hid[NATOMS * FD];    // silu hidden
__device__ float g_phi[NATOMS * FD];    // phi (first F columns only)
__device__ float g_H[MBEADS * FD];      // bead accumulator
__device__ float g_cnt[MBEADS];
__device__ float g_icnt[MBEADS];
__device__ float g_eemb[EHALF * 17];    // per-edge: rbf*env (16) + env
__device__ float g_aemb[NATOMS * 17];   // per-atom (CG cutoff): rbf*env (16) + env

// vectorized global reduction (sm_90+)
__device__ __forceinline__ void red4(float* addr, float x, float y, float z, float w) {
    asm volatile("red.global.add.v4.f32 [%0], {%1,%2,%3,%4};"
                 :: "l"(addr), "f"(x), "f"(y), "f"(z), "f"(w) : "memory");
}

// ---------------- init / precompute ----------------
__global__ void k_zero() {
    int i = blockIdx.x * blockDim.x + threadIdx.x;
    if (i < MBEADS * FD) g_H[i] = 0.f;
    if (i < MBEADS) g_cnt[i] = 0.f;
}

__global__ void k_init(const int* __restrict__ z, const int* __restrict__ cg_z,
                       const int* __restrict__ map,
                       const float* __restrict__ emb_atom,
                       const float* __restrict__ emb_res) {
    int idx = blockIdx.x * blockDim.x + threadIdx.x;
    if (idx >= NATOMS * 32) return;
    int a = idx >> 5, c = idx & 31;
    int f = c * 4;
    float4 v;
    if (f < 64) v = *(const float4*)(emb_atom + (size_t)z[a] * 64 + f);
    else        v = *(const float4*)(emb_res + (size_t)cg_z[map[a]] * 64 + (f - 64));
    *(float4*)(g_h + (size_t)a * FD + f) = v;
    if (c == 0) atomicAdd(&g_cnt[map[a]], 1.0f);
}

__global__ void k_icnt() {
    int m = blockIdx.x * blockDim.x + threadIdx.x;
    if (m < MBEADS) g_icnt[m] = 1.0f / fmaxf(g_cnt[m], 1.0f);
}

__device__ __forceinline__ void rbf_env(float d, float cut, float* out17) {
    float env = 0.f;
    if (d < cut) env = 0.5f * (cosf(PIF * d / cut) + 1.0f);
    if (env == 0.f) {
        #pragma unroll
        for (int k = 0; k < 17; k++) out17[k] = 0.f;
        return;
    }
    float invd = 1.0f / d;
    float w = PIF / cut * d;
    #pragma unroll
    for (int k = 0; k < 16; k++)
        out17[k] = env * sinf((float)(k + 1) * w) * invd;
    out17[16] = env;
}

__global__ void k_epre(const int* __restrict__ nbr, const float* __restrict__ xyz) {
    int e = blockIdx.x * blockDim.x + threadIdx.x;
    if (e >= EHALF) return;
    int a = nbr[2 * e], b = nbr[2 * e + 1];
    float dx = xyz[3 * b + 0] - xyz[3 * a + 0];
    float dy = xyz[3 * b + 1] - xyz[3 * a + 1];
    float dz = xyz[3 * b + 2] - xyz[3 * a + 2];
    float d = sqrtf(dx * dx + dy * dy + dz * dz + 3e-15f);
    float o[17];
    rbf_env(d, 5.0f, o);
    #pragma unroll
    for (int k = 0; k < 17; k++) g_eemb[(size_t)e * 17 + k] = o[k];
}

__global__ void k_aemb(const int* __restrict__ map, const float* __restrict__ xyz,
                       const float* __restrict__ cg_xyz) {
    int a = blockIdx.x * blockDim.x + threadIdx.x;
    if (a >= NATOMS) return;
    int m = map[a];
    float dx = xyz[3 * a + 0] - cg_xyz[3 * m + 0];
    float dy = xyz[3 * a + 1] - cg_xyz[3 * m + 1];
    float dz = xyz[3 * a + 2] - cg_xyz[3 * m + 2];
    float d = sqrtf(dx * dx + dy * dy + dz * dz + 3e-15f);
    float o[17];
    rbf_env(d, 20.0f, o);
    #pragma unroll
    for (int k = 0; k < 17; k++) g_aemb[(size_t)a * 17 + k] = o[k];
}

// ---------------- SGEMM: C[n,128] = A[n,128] @ W[128, ldw][:, :128] + bias ----
// 256 threads, 64-row x 128-col tile, thread micro-tile 8x4, BK=32.
__global__ void k_gemm(const float* __restrict__ A, const float* __restrict__ W,
                       int ldw, const float* __restrict__ bias,
                       float* __restrict__ C, int n, int dosilu) {
    __shared__ float As[32 * 68];   // transposed A tile [kk][row], padded
    __shared__ float Ws[32 * 128];  // W tile [kk][col]
    int tid = threadIdx.x;
    int tx = tid & 31, ty = tid >> 5;
    int row0 = blockIdx.x * 64;
    float acc[8][4];
    #pragma unroll
    for (int i = 0; i < 8; i++)
        #pragma unroll
        for (int j = 0; j < 4; j++) acc[i][j] = 0.f;

    for (int k0 = 0; k0 < 128; k0 += 32) {
        #pragma unroll
        for (int j = 0; j < 2; j++) {
            int q = tid + j * 256;
            int r = q >> 3, c4 = q & 7;
            float4 v = make_float4(0.f, 0.f, 0.f, 0.f);
            if (row0 + r < n)
                v = *(const float4*)(A + (size_t)(row0 + r) * 128 + k0 + c4 * 4);
            As[(c4 * 4 + 0) * 68 + r] = v.x;
            As[(c4 * 4 + 1) * 68 + r] = v.y;
            As[(c4 * 4 + 2) * 68 + r] = v.z;
            As[(c4 * 4 + 3) * 68 + r] = v.w;
        }
        #pragma unroll
        for (int j = 0; j < 4; j++) {
            int q = tid + j * 256;
            int kk = q >> 5, c4 = q & 31;
            *(float4*)(Ws + kk * 128 + c4 * 4) =
                *(const float4*)(W + (size_t)(k0 + kk) * ldw + c4 * 4);
        }
        __syncthreads();
        #pragma unroll
        for (int kk = 0; kk < 32; kk++) {
            float4 a0 = *(const float4*)(As + kk * 68 + ty * 8);
            float4 a1 = *(const float4*)(As + kk * 68 + ty * 8 + 4);
            float4 b  = *(const float4*)(Ws + kk * 128 + tx * 4);
            float av[8] = {a0.x, a0.y, a0.z, a0.w, a1.x, a1.y, a1.z, a1.w};
            float bv[4] = {b.x, b.y, b.z, b.w};
            #pragma unroll
            for (int i = 0; i < 8; i++)
                #pragma unroll
                for (int j = 0; j < 4; j++)
                    acc[i][j] += av[i] * bv[j];
        }
        __syncthreads();
    }

    float4 bq = *(const float4*)(bias + tx * 4);
    float bb[4] = {bq.x, bq.y, bq.z, bq.w};
    #pragma unroll
    for (int i = 0; i < 8; i++) {
        int r = row0 + ty * 8 + i;
        if (r < n) {
            float o[4];
            #pragma unroll
            for (int j = 0; j < 4; j++) {
                float x = acc[i][j] + bb[j];
                if (dosilu) x = x / (1.0f + __expf(-x));
                o[j] = x;
            }
            *(float4*)(C + (size_t)r * 128 + tx * 4) =
                make_float4(o[0], o[1], o[2], o[3]);
        }
    }
}

// ---------------- edge message pass: h[a] += emb*phi[b]; h[b] += emb*phi[a] ---
__global__ void k_edge_conv(const int* __restrict__ nbr,
                            const float* __restrict__ Wd,   // (16, 384) use cols<128
                            const float* __restrict__ bd) { // (384)     use <128
    __shared__ float sW[16 * 128];
    __shared__ float sb[128];
    for (int t = threadIdx.x; t < 16 * 128; t += blockDim.x)
        sW[t] = Wd[(t >> 7) * 384 + (t & 127)];
    if (threadIdx.x < 128) sb[threadIdx.x] = bd[threadIdx.x];
    __syncthreads();

    int lane = threadIdx.x & 31;
    int w  = (blockIdx.x * blockDim.x + threadIdx.x) >> 5;
    int nw = (gridDim.x * blockDim.x) >> 5;
    float4 bv = *(const float4*)(sb + lane * 4);

    for (int e = w; e < EHALF; e += nw) {
        float rv = (lane < 17) ? g_eemb[(size_t)e * 17 + lane] : 0.f;
        float env = __shfl_sync(0xffffffffu, rv, 16);
        if (env == 0.f) continue;   // uniform across warp
        int a = nbr[2 * e], b = nbr[2 * e + 1];
        float ex = env * bv.x, ey = env * bv.y, ez = env * bv.z, ew = env * bv.w;
        #pragma unroll
        for (int k = 0; k < 16; k++) {
            float r = __shfl_sync(0xffffffffu, rv, k);
            float4 wv = *(const float4*)(sW + k * 128 + lane * 4);
            ex += r * wv.x; ey += r * wv.y; ez += r * wv.z; ew += r * wv.w;
        }
        float4 pb = *(const float4*)(g_phi + (size_t)b * FD + lane * 4);
        float4 pa = *(const float4*)(g_phi + (size_t)a * FD + lane * 4);
        red4(g_h + (size_t)a * FD + lane * 4, ex * pb.x, ey * pb.y, ez * pb.z, ew * pb.w);
        red4(g_h + (size_t)b * FD + lane * 4, ex * pa.x, ey * pa.y, ez * pa.z, ew * pa.w);
    }
}

// ---------------- CG pass: H[map[a]] += emb(d_iI)*phi[a] / cnt ---------------
__global__ void k_cg_conv(const int* __restrict__ map,
                          const float* __restrict__ Wd,
                          const float* __restrict__ bd) {
    __shared__ float sW[16 * 128];
    __shared__ float sb[128];
    for (int t = threadIdx.x; t < 16 * 128; t += blockDim.x)
        sW[t] = Wd[(t >> 7) * 384 + (t & 127)];
    if (threadIdx.x < 128) sb[threadIdx.x] = bd[threadIdx.x];
    __syncthreads();

    int lane = threadIdx.x & 31;
    int w  = (blockIdx.x * blockDim.x + threadIdx.x) >> 5;
    int nw = (gridDim.x * blockDim.x) >> 5;
    float4 bv = *(const float4*)(sb + lane * 4);

    for (int a = w; a < NATOMS; a += nw) {
        float rv = (lane < 17) ? g_aemb[(size_t)a * 17 + lane] : 0.f;
        float env = __shfl_sync(0xffffffffu, rv, 16);
        if (env == 0.f) continue;
        float ex = env * bv.x, ey = env * bv.y, ez = env * bv.z, ew = env * bv.w;
        #pragma unroll
        for (int k = 0; k < 16; k++) {
            float r = __shfl_sync(0xffffffffu, rv, k);
            float4 wv = *(const float4*)(sW + k * 128 + lane * 4);
            ex += r * wv.x; ey += r * wv.y; ez += r * wv.z; ew += r * wv.w;
        }
        float4 p = *(const float4*)(g_phi + (size_t)a * FD + lane * 4);
        int m = map[a];
        float ic = g_icnt[m];
        red4(g_H + (size_t)m * FD + lane * 4,
             ex * p.x * ic, ey * p.y * ic, ez * p.z * ic, ew * p.w * ic);
    }
}

// ---------------- H snapshot after conv0 message update ----------------------
__global__ void k_snapshot(const int* __restrict__ map) {
    int idx = blockIdx.x * blockDim.x + threadIdx.x;
    if (idx >= NATOMS * 32) return;
    int a = idx >> 5, c = idx & 31;
    int m = map[a];
    float ic = g_icnt[m];
    float4 v = *(const float4*)(g_h + (size_t)a * FD + c * 4);
    red4(g_H + (size_t)m * FD + c * 4, v.x * ic, v.y * ic, v.z * ic, v.w * ic);
}

// ---------------- output: [H (M,F), h (N,F)] ---------------------------------
__global__ void k_out(float* __restrict__ out) {
    int idx = blockIdx.x * blockDim.x + threadIdx.x;
    const int nH = MBEADS * FD / 4;
    const int tot = nH + NATOMS * FD / 4;
    if (idx >= tot) return;
    float4 v;
    if (idx < nH) v = ((const float4*)g_H)[idx];
    else          v = ((const float4*)g_h)[idx - nH];
    ((float4*)out)[idx] = v;
}

// ---------------- launch ------------------------------------------------------
extern "C" void kernel_launch(void* const* d_in, const int* in_sizes, int n_in,
                              void* d_out, int out_size) {
    const int*   z        = (const int*)d_in[0];
    const float* xyz      = (const float*)d_in[1];
    const int*   cg_z     = (const int*)d_in[2];
    const float* cg_xyz   = (const float*)d_in[3];
    const int*   mapping  = (const int*)d_in[4];
    const int*   nbr      = (const int*)d_in[5];
    // d_in[6] cg_nbr_list, d_in[7] ic: unused (dead in reference output)
    const float* emb_atom = (const float*)d_in[8];
    const float* emb_res  = (const float*)d_in[9];
    const float* Wm1 = (const float*)d_in[10];
    const float* bm1 = (const float*)d_in[11];
    const float* Wm2 = (const float*)d_in[12];
    const float* bm2 = (const float*)d_in[13];
    const float* Wdm = (const float*)d_in[14];
    const float* bdm = (const float*)d_in[15];
    const float* Wc1 = (const float*)d_in[16];
    const float* bc1 = (const float*)d_in[17];
    const float* Wc2 = (const float*)d_in[18];
    const float* bc2 = (const float*)d_in[19];
    const float* Wdc = (const float*)d_in[20];
    const float* bdc = (const float*)d_in[21];

    float *ph = nullptr, *phid = nullptr, *pphi = nullptr;
    cudaGetSymbolAddress((void**)&ph, g_h);
    cudaGetSymbolAddress((void**)&phid, g_hid);
    cudaGetSymbolAddress((void**)&pphi, g_phi);

    k_zero<<<(MBEADS * FD + 255) / 256, 256>>>();
    k_init<<<(NATOMS * 32 + 255) / 256, 256>>>(z, cg_z, mapping, emb_atom, emb_res);
    k_icnt<<<(MBEADS + 255) / 256, 256>>>();
    k_epre<<<(EHALF + 255) / 256, 256>>>(nbr, xyz);
    k_aemb<<<(NATOMS + 255) / 256, 256>>>(mapping, xyz, cg_xyz);

    const int gb = (NATOMS + 63) / 64;
    for (int i = 0; i < 2; i++) {
        // message block: phi = silu(h@Wm1+bm1)@Wm2[:, :F]+bm2[:F]
        k_gemm<<<gb, 256>>>(ph,   Wm1 + (size_t)i * 128 * 128, 128, bm1 + i * 128, phid, NATOMS, 1);
        k_gemm<<<gb, 256>>>(phid, Wm2 + (size_t)i * 128 * 384, 384, bm2 + i * 384, pphi, NATOMS, 0);
        k_edge_conv<<<592, 256>>>(nbr, Wdm + (size_t)i * 16 * 384, bdm + i * 384);
        if (i == 0)
            k_snapshot<<<(NATOMS * 32 + 255) / 256, 256>>>(mapping);
        // CG block: only s0 feeds H
        k_gemm<<<gb, 256>>>(ph,   Wc1 + (size_t)i * 128 * 128, 128, bc1 + i * 128, phid, NATOMS, 1);
        k_gemm<<<gb, 256>>>(phid, Wc2 + (size_t)i * 128 * 384, 384, bc2 + i * 384, pphi, NATOMS, 0);
        k_cg_conv<<<592, 256>>>(mapping, Wdc + (size_t)i * 16 * 384, bdc + i * 384);
    }
    k_out<<<((MBEADS + NATOMS) * 32 + 255) / 256, 256>>>((float*)d_out);
}